// round 6
// baseline (speedup 1.0000x reference)
#include <cuda_runtime.h>
#include <cuda_fp16.h>
#include <math.h>
#include <stdint.h>

#define NN 100000
#define NE 1600000
#define ET (NE + NN)
#define LRELU 0.2f

// ---------- scratch ----------
__device__ __half g_h[(size_t)NN * 128];    // fp16 post-GEMM features
__device__ float g_feat[(size_t)NN * 128];
__device__ float g_als[(size_t)NN * 8];
__device__ float g_ald[(size_t)NN * 8];
__device__ int   g_rowptr[NN + 1];
__device__ int   g_cnt[NN];
__device__ int   g_srcs[ET];
__device__ int   g_part[128];

// ---------------------- CSR build ----------------------
__global__ void k_init_cnt(int n) {
    int i = blockIdx.x * blockDim.x + threadIdx.x;
    if (i < n) g_cnt[i] = 1;
}
__global__ void k_count(const int* __restrict__ dst, int e) {
    int i = blockIdx.x * blockDim.x + threadIdx.x;
    if (i < e) atomicAdd(&g_cnt[dst[i]], 1);
}
__global__ void k_scan1(int n) {
    __shared__ int sh[1024];
    int tid = threadIdx.x;
    int i = blockIdx.x * 1024 + tid;
    int v = (i < n) ? g_cnt[i] : 0;
    sh[tid] = v;
    __syncthreads();
    #pragma unroll
    for (int o = 1; o < 1024; o <<= 1) {
        int t = (tid >= o) ? sh[tid - o] : 0;
        __syncthreads();
        sh[tid] += t;
        __syncthreads();
    }
    if (i < n) g_rowptr[i] = sh[tid] - v;
    if (tid == 1023) g_part[blockIdx.x] = sh[1023];
}
__global__ void k_scan2(int nb) {
    __shared__ int sh[128];
    int tid = threadIdx.x;
    int v = (tid < nb) ? g_part[tid] : 0;
    sh[tid] = v;
    __syncthreads();
    #pragma unroll
    for (int o = 1; o < 128; o <<= 1) {
        int t = (tid >= o) ? sh[tid - o] : 0;
        __syncthreads();
        sh[tid] += t;
        __syncthreads();
    }
    if (tid < nb) g_part[tid] = sh[tid] - v;
}
// scan finalize + self-loop placement + cursor init (fused)
__global__ void k_scan3(int n, int etot) {
    int i = blockIdx.x * 1024 + threadIdx.x;
    if (i < n) {
        int p = g_rowptr[i] + g_part[blockIdx.x];
        g_rowptr[i] = p;
        g_srcs[p] = i;
        g_cnt[i] = p + 1;
    }
    if (i == 0) g_rowptr[n] = etot;
}
__global__ void k_scatter(const int* __restrict__ src, const int* __restrict__ dst, int e) {
    int i = blockIdx.x * blockDim.x + threadIdx.x;
    if (i < e) {
        int pos = atomicAdd(&g_cnt[dst[i]], 1);
        g_srcs[pos] = src[i];
    }
}

// ---------------------- tf32 helpers ----------------------
__device__ __forceinline__ uint32_t f2tf32(float x) {
    uint32_t r;
    asm("cvt.rna.tf32.f32 %0, %1;" : "=r"(r) : "f"(x));
    return r;
}
#define MMA_TF32(d, a, b) \
    asm volatile("mma.sync.aligned.m16n8k8.row.col.f32.tf32.tf32.f32 " \
        "{%0,%1,%2,%3}, {%4,%5,%6,%7}, {%8,%9}, {%0,%1,%2,%3};" \
        : "+f"((d)[0]), "+f"((d)[1]), "+f"((d)[2]), "+f"((d)[3]) \
        : "r"((a)[0]), "r"((a)[1]), "r"((a)[2]), "r"((a)[3]), \
          "r"((b)[0]), "r"((b)[1]))

// ---------------------- TC GEMM 128x128 + attn coefs (8 heads x 16) ----------------------
__global__ __launch_bounds__(256) void k_gemm_attn8_tc(
    const float* __restrict__ A, const float* __restrict__ W,
    const float* __restrict__ asr, const float* __restrict__ adr,
    __half* __restrict__ H, float* __restrict__ als, float* __restrict__ ald, int n)
{
    __shared__ __align__(16) uint32_t As[128 * 36];
    __shared__ __align__(16) uint32_t Bs[32 * 136];
    int tid = threadIdx.x;
    int wid = tid >> 5, lane = tid & 31;
    int warp_m = wid >> 1, warp_n = wid & 1;
    int g = lane >> 2, c = lane & 3;
    int row0 = blockIdx.x * 128;

    float acc[2][8][4];
    #pragma unroll
    for (int mt = 0; mt < 2; mt++)
        #pragma unroll
        for (int nt = 0; nt < 8; nt++)
            #pragma unroll
            for (int j = 0; j < 4; j++) acc[mt][nt][j] = 0.f;

    for (int k0 = 0; k0 < 128; k0 += 32) {
        #pragma unroll
        for (int l = 0; l < 4; l++) {
            int idx = tid + l * 256;
            int r = idx >> 3, kq = idx & 7;
            int gr = row0 + r;
            float4 v = make_float4(0.f, 0.f, 0.f, 0.f);
            if (gr < n) v = *(const float4*)(A + (size_t)gr * 128 + k0 + kq * 4);
            uint4 u = {f2tf32(v.x), f2tf32(v.y), f2tf32(v.z), f2tf32(v.w)};
            *(uint4*)&As[r * 36 + kq * 4] = u;
        }
        #pragma unroll
        for (int l = 0; l < 4; l++) {
            int idx = tid + l * 256;
            int kr = idx >> 5, cq = idx & 31;
            float4 v = *(const float4*)(W + (size_t)(k0 + kr) * 128 + cq * 4);
            uint4 u = {f2tf32(v.x), f2tf32(v.y), f2tf32(v.z), f2tf32(v.w)};
            *(uint4*)&Bs[kr * 136 + cq * 4] = u;
        }
        __syncthreads();
        #pragma unroll
        for (int ks = 0; ks < 4; ks++) {
            uint32_t bf[8][2];
            #pragma unroll
            for (int nt = 0; nt < 8; nt++) {
                int col = warp_n * 64 + nt * 8 + g;
                bf[nt][0] = Bs[(ks * 8 + c) * 136 + col];
                bf[nt][1] = Bs[(ks * 8 + c + 4) * 136 + col];
            }
            #pragma unroll
            for (int mt = 0; mt < 2; mt++) {
                int row = warp_m * 32 + mt * 16 + g;
                uint32_t af[4];
                af[0] = As[row * 36 + ks * 8 + c];
                af[1] = As[(row + 8) * 36 + ks * 8 + c];
                af[2] = As[row * 36 + ks * 8 + c + 4];
                af[3] = As[(row + 8) * 36 + ks * 8 + c + 4];
                #pragma unroll
                for (int nt = 0; nt < 8; nt++) MMA_TF32(acc[mt][nt], af, bf[nt]);
            }
        }
        __syncthreads();
    }

    #pragma unroll
    for (int mt = 0; mt < 2; mt++) {
        int r_lo = row0 + warp_m * 32 + mt * 16 + g;
        int r_hi = r_lo + 8;
        float sA0[4] = {0, 0, 0, 0}, sA1[4] = {0, 0, 0, 0};
        float sD0[4] = {0, 0, 0, 0}, sD1[4] = {0, 0, 0, 0};
        #pragma unroll
        for (int nt = 0; nt < 8; nt++) {
            int col = warp_n * 64 + nt * 8 + c * 2;
            int hh = nt >> 1;
            float as0 = asr[col], as1 = asr[col + 1];
            float ad0 = adr[col], ad1 = adr[col + 1];
            float* d = acc[mt][nt];
            sA0[hh] = fmaf(d[0], as0, fmaf(d[1], as1, sA0[hh]));
            sA1[hh] = fmaf(d[2], as0, fmaf(d[3], as1, sA1[hh]));
            sD0[hh] = fmaf(d[0], ad0, fmaf(d[1], ad1, sD0[hh]));
            sD1[hh] = fmaf(d[2], ad0, fmaf(d[3], ad1, sD1[hh]));
            if (r_lo < n) *(__half2*)(H + (size_t)r_lo * 128 + col) = __floats2half2_rn(d[0], d[1]);
            if (r_hi < n) *(__half2*)(H + (size_t)r_hi * 128 + col) = __floats2half2_rn(d[2], d[3]);
        }
        #pragma unroll
        for (int hh = 0; hh < 4; hh++) {
            sA0[hh] += __shfl_xor_sync(0xFFFFFFFFu, sA0[hh], 1);
            sA0[hh] += __shfl_xor_sync(0xFFFFFFFFu, sA0[hh], 2);
            sA1[hh] += __shfl_xor_sync(0xFFFFFFFFu, sA1[hh], 1);
            sA1[hh] += __shfl_xor_sync(0xFFFFFFFFu, sA1[hh], 2);
            sD0[hh] += __shfl_xor_sync(0xFFFFFFFFu, sD0[hh], 1);
            sD0[hh] += __shfl_xor_sync(0xFFFFFFFFu, sD0[hh], 2);
            sD1[hh] += __shfl_xor_sync(0xFFFFFFFFu, sD1[hh], 1);
            sD1[hh] += __shfl_xor_sync(0xFFFFFFFFu, sD1[hh], 2);
        }
        if (c == 0) {
            #pragma unroll
            for (int hh = 0; hh < 4; hh++) {
                int hgl = warp_n * 4 + hh;
                if (r_lo < n) { als[(size_t)r_lo * 8 + hgl] = sA0[hh]; ald[(size_t)r_lo * 8 + hgl] = sD0[hh]; }
                if (r_hi < n) { als[(size_t)r_hi * 8 + hgl] = sA1[hh]; ald[(size_t)r_hi * 8 + hgl] = sD1[hh]; }
            }
        }
    }
}

// ---------------------- TC GEMM 128x64 + attn coefs (1 head x 64) ----------------------
__global__ __launch_bounds__(256) void k_gemm_attn1_tc(
    const float* __restrict__ A, const float* __restrict__ W,
    const float* __restrict__ asr, const float* __restrict__ adr,
    __half* __restrict__ H, float* __restrict__ als, float* __restrict__ ald, int n)
{
    __shared__ __align__(16) uint32_t As[128 * 36];
    __shared__ __align__(16) uint32_t Bs[32 * 72];
    int tid = threadIdx.x;
    int wid = tid >> 5, lane = tid & 31;
    int g = lane >> 2, c = lane & 3;
    int row0 = blockIdx.x * 128;

    float acc[8][4];
    #pragma unroll
    for (int nt = 0; nt < 8; nt++)
        #pragma unroll
        for (int j = 0; j < 4; j++) acc[nt][j] = 0.f;

    for (int k0 = 0; k0 < 128; k0 += 32) {
        #pragma unroll
        for (int l = 0; l < 4; l++) {
            int idx = tid + l * 256;
            int r = idx >> 3, kq = idx & 7;
            int gr = row0 + r;
            float4 v = make_float4(0.f, 0.f, 0.f, 0.f);
            if (gr < n) v = *(const float4*)(A + (size_t)gr * 128 + k0 + kq * 4);
            uint4 u = {f2tf32(v.x), f2tf32(v.y), f2tf32(v.z), f2tf32(v.w)};
            *(uint4*)&As[r * 36 + kq * 4] = u;
        }
        #pragma unroll
        for (int l = 0; l < 2; l++) {
            int idx = tid + l * 256;
            int kr = idx >> 4, cq = idx & 15;
            float4 v = *(const float4*)(W + (size_t)(k0 + kr) * 64 + cq * 4);
            uint4 u = {f2tf32(v.x), f2tf32(v.y), f2tf32(v.z), f2tf32(v.w)};
            *(uint4*)&Bs[kr * 72 + cq * 4] = u;
        }
        __syncthreads();
        #pragma unroll
        for (int ks = 0; ks < 4; ks++) {
            int row = wid * 16 + g;
            uint32_t af[4];
            af[0] = As[row * 36 + ks * 8 + c];
            af[1] = As[(row + 8) * 36 + ks * 8 + c];
            af[2] = As[row * 36 + ks * 8 + c + 4];
            af[3] = As[(row + 8) * 36 + ks * 8 + c + 4];
            #pragma unroll
            for (int nt = 0; nt < 8; nt++) {
                int col = nt * 8 + g;
                uint32_t bf[2];
                bf[0] = Bs[(ks * 8 + c) * 72 + col];
                bf[1] = Bs[(ks * 8 + c + 4) * 72 + col];
                MMA_TF32(acc[nt], af, bf);
            }
        }
        __syncthreads();
    }

    int r_lo = row0 + wid * 16 + g;
    int r_hi = r_lo + 8;
    float sA0 = 0.f, sA1 = 0.f, sD0 = 0.f, sD1 = 0.f;
    #pragma unroll
    for (int nt = 0; nt < 8; nt++) {
        int col = nt * 8 + c * 2;
        float as0 = asr[col], as1 = asr[col + 1];
        float ad0 = adr[col], ad1 = adr[col + 1];
        float* d = acc[nt];
        sA0 = fmaf(d[0], as0, fmaf(d[1], as1, sA0));
        sA1 = fmaf(d[2], as0, fmaf(d[3], as1, sA1));
        sD0 = fmaf(d[0], ad0, fmaf(d[1], ad1, sD0));
        sD1 = fmaf(d[2], ad0, fmaf(d[3], ad1, sD1));
        if (r_lo < n) *(__half2*)(H + (size_t)r_lo * 64 + col) = __floats2half2_rn(d[0], d[1]);
        if (r_hi < n) *(__half2*)(H + (size_t)r_hi * 64 + col) = __floats2half2_rn(d[2], d[3]);
    }
    sA0 += __shfl_xor_sync(0xFFFFFFFFu, sA0, 1); sA0 += __shfl_xor_sync(0xFFFFFFFFu, sA0, 2);
    sA1 += __shfl_xor_sync(0xFFFFFFFFu, sA1, 1); sA1 += __shfl_xor_sync(0xFFFFFFFFu, sA1, 2);
    sD0 += __shfl_xor_sync(0xFFFFFFFFu, sD0, 1); sD0 += __shfl_xor_sync(0xFFFFFFFFu, sD0, 2);
    sD1 += __shfl_xor_sync(0xFFFFFFFFu, sD1, 1); sD1 += __shfl_xor_sync(0xFFFFFFFFu, sD1, 2);
    if (c == 0) {
        if (r_lo < n) { als[r_lo] = sA0; ald[r_lo] = sD0; }
        if (r_hi < n) { als[r_hi] = sA1; ald[r_hi] = sD1; }
    }
}

// ---------------------- aggregation (8 heads x 16) + fused LN+ReLU, pipelined ----------------------
__global__ __launch_bounds__(256) void k_agg8(
    const __half* __restrict__ H, const float* __restrict__ als,
    const float* __restrict__ ald, const float* __restrict__ bias,
    const float* __restrict__ lng, const float* __restrict__ lnb,
    float* __restrict__ out, int n)
{
    int w = (blockIdx.x * blockDim.x + threadIdx.x) >> 5;
    if (w >= n) return;
    int lane = threadIdx.x & 31;
    int s = g_rowptr[w], e2 = g_rowptr[w + 1];
    int hd = lane >> 2;
    int d0 = lane * 4;
    float myald = ald[(size_t)w * 8 + (lane & 7)];
    float denom = 0.f;
    float ax = 0.f, ay = 0.f, az = 0.f, aw = 0.f;

    // software-pipelined chunks of 4 with src prefetch (pad with -1)
    int sv[4], svn[4];
    #pragma unroll
    for (int j = 0; j < 4; j++) sv[j] = (s + j < e2) ? g_srcs[s + j] : -1;

    for (int i = s; i < e2; i += 4) {
        int inext = i + 4;
        #pragma unroll
        for (int j = 0; j < 4; j++) svn[j] = (inext + j < e2) ? g_srcs[inext + j] : -1;

        float wv[4] = {0.f, 0.f, 0.f, 0.f};
        if (lane < 8) {
            #pragma unroll
            for (int j = 0; j < 4; j++) {
                if (sv[j] >= 0) {
                    float x = als[(size_t)sv[j] * 8 + lane] + myald;
                    x = (x > 0.f) ? x : LRELU * x;
                    wv[j] = __expf(x);
                    denom += wv[j];
                }
            }
        }
        uint2 raw[4];
        #pragma unroll
        for (int j = 0; j < 4; j++) {
            int idx = (sv[j] >= 0) ? sv[j] : 0;
            raw[j] = *(const uint2*)(H + (size_t)idx * 128 + d0);
        }
        #pragma unroll
        for (int j = 0; j < 4; j++) {
            float a = __shfl_sync(0xFFFFFFFFu, wv[j], hd);
            float2 f01 = __half22float2(*(__half2*)&raw[j].x);
            float2 f23 = __half22float2(*(__half2*)&raw[j].y);
            ax = fmaf(a, f01.x, ax); ay = fmaf(a, f01.y, ay);
            az = fmaf(a, f23.x, az); aw = fmaf(a, f23.y, aw);
        }
        #pragma unroll
        for (int j = 0; j < 4; j++) sv[j] = svn[j];
    }

    float inv = 1.f / __shfl_sync(0xFFFFFFFFu, denom, hd);
    float4 bv = *(const float4*)(bias + d0);
    float ox = fmaf(ax, inv, bv.x);
    float oy = fmaf(ay, inv, bv.y);
    float oz = fmaf(az, inv, bv.z);
    float ow = fmaf(aw, inv, bv.w);

    float sm = ox + oy + oz + ow;
    #pragma unroll
    for (int o = 16; o; o >>= 1) sm += __shfl_xor_sync(0xFFFFFFFFu, sm, o);
    float mu = sm * (1.f / 128.f);
    float dx = ox - mu, dy = oy - mu, dz = oz - mu, dw = ow - mu;
    float q = dx * dx + dy * dy + dz * dz + dw * dw;
    #pragma unroll
    for (int o = 16; o; o >>= 1) q += __shfl_xor_sync(0xFFFFFFFFu, q, o);
    float rstd = rsqrtf(q * (1.f / 128.f) + 1e-5f);
    float4 gg = *(const float4*)(lng + d0);
    float4 bb = *(const float4*)(lnb + d0);
    ox = fmaxf(fmaf(dx * rstd, gg.x, bb.x), 0.f);
    oy = fmaxf(fmaf(dy * rstd, gg.y, bb.y), 0.f);
    oz = fmaxf(fmaf(dz * rstd, gg.z, bb.z), 0.f);
    ow = fmaxf(fmaf(dw * rstd, gg.w, bb.w), 0.f);
    float4 o4 = {ox, oy, oz, ow};
    *(float4*)(out + (size_t)w * 128 + d0) = o4;
}

// ---------------------- aggregation (1 head x 64) + log_softmax, pipelined ----------------------
__global__ __launch_bounds__(256) void k_agg1_lsm(
    const __half* __restrict__ H, const float* __restrict__ als,
    const float* __restrict__ ald, const float* __restrict__ bias,
    float* __restrict__ out, int n)
{
    int w = (blockIdx.x * blockDim.x + threadIdx.x) >> 5;
    if (w >= n) return;
    int lane = threadIdx.x & 31;
    int s = g_rowptr[w], e2 = g_rowptr[w + 1];
    float aldv = ald[w];
    int d0 = lane * 2;

    float denom = 0.f, acc0 = 0.f, acc1 = 0.f;
    int sv[4], svn[4];
    #pragma unroll
    for (int j = 0; j < 4; j++) sv[j] = (s + j < e2) ? g_srcs[s + j] : -1;

    for (int i = s; i < e2; i += 4) {
        int inext = i + 4;
        #pragma unroll
        for (int j = 0; j < 4; j++) svn[j] = (inext + j < e2) ? g_srcs[inext + j] : -1;

        float wv[4] = {0.f, 0.f, 0.f, 0.f};
        #pragma unroll
        for (int j = 0; j < 4; j++) {
            if (sv[j] >= 0) {
                float x = als[sv[j]] + aldv;
                x = (x > 0.f) ? x : LRELU * x;
                wv[j] = __expf(x);
                denom += wv[j];
            }
        }
        __half2 hv[4];
        #pragma unroll
        for (int j = 0; j < 4; j++) {
            int idx = (sv[j] >= 0) ? sv[j] : 0;
            hv[j] = *(const __half2*)(H + (size_t)idx * 64 + d0);
        }
        #pragma unroll
        for (int j = 0; j < 4; j++) {
            float2 f = __half22float2(hv[j]);
            acc0 = fmaf(wv[j], f.x, acc0);
            acc1 = fmaf(wv[j], f.y, acc1);
        }
        #pragma unroll
        for (int j = 0; j < 4; j++) sv[j] = svn[j];
    }
    float inv = 1.f / denom;
    float v0 = fmaf(acc0, inv, bias[d0]);
    float v1 = fmaf(acc1, inv, bias[d0 + 1]);
    float mx = fmaxf(v0, v1);
    #pragma unroll
    for (int o = 16; o; o >>= 1) mx = fmaxf(mx, __shfl_xor_sync(0xFFFFFFFFu, mx, o));
    float se = __expf(v0 - mx) + __expf(v1 - mx);
    #pragma unroll
    for (int o = 16; o; o >>= 1) se += __shfl_xor_sync(0xFFFFFFFFu, se, o);
    float lse = mx + __logf(se);
    out[(size_t)w * 64 + d0] = v0 - lse;
    out[(size_t)w * 64 + d0 + 1] = v1 - lse;
}

// ---------------------- launcher ----------------------
extern "C" void kernel_launch(void* const* d_in, const int* in_sizes, int n_in,
                              void* d_out, int out_size) {
    const float* x   = (const float*)d_in[0];
    const int*   ei  = (const int*)d_in[1];
    const float* W0  = (const float*)d_in[2];
    const float* as0 = (const float*)d_in[3];
    const float* ad0 = (const float*)d_in[4];
    const float* b0  = (const float*)d_in[5];
    const float* W1  = (const float*)d_in[6];
    const float* as1 = (const float*)d_in[7];
    const float* ad1 = (const float*)d_in[8];
    const float* b1  = (const float*)d_in[9];
    const float* W2  = (const float*)d_in[10];
    const float* as2 = (const float*)d_in[11];
    const float* ad2 = (const float*)d_in[12];
    const float* b2  = (const float*)d_in[13];
    const float* ln1g = (const float*)d_in[14];
    const float* ln1b = (const float*)d_in[15];
    const float* ln2g = (const float*)d_in[16];
    const float* ln2b = (const float*)d_in[17];
    float* out = (float*)d_out;

    const int n = in_sizes[0] / 128;
    const int e = in_sizes[1] / 2;
    const int etot = e + n;
    const int* src = ei;
    const int* dst = ei + e;

    __half* h;
    float *feat, *als, *ald;
    cudaGetSymbolAddress((void**)&h, g_h);
    cudaGetSymbolAddress((void**)&feat, g_feat);
    cudaGetSymbolAddress((void**)&als, g_als);
    cudaGetSymbolAddress((void**)&ald, g_ald);

    const int nb_nodes256 = (n + 255) / 256;
    const int nb_edges256 = (e + 255) / 256;
    const int nb_scan = (n + 1023) / 1024;
    const int nb_warp = (n * 32 + 255) / 256;
    const int nb_gemm = (n + 127) / 128;

    k_init_cnt<<<nb_nodes256, 256>>>(n);
    k_count<<<nb_edges256, 256>>>(dst, e);
    k_scan1<<<nb_scan, 1024>>>(n);
    k_scan2<<<1, 128>>>(nb_scan);
    k_scan3<<<nb_scan, 1024>>>(n, etot);
    k_scatter<<<nb_edges256, 256>>>(src, dst, e);

    k_gemm_attn8_tc<<<nb_gemm, 256>>>(x, W0, as0, ad0, h, als, ald, n);
    k_agg8<<<nb_warp, 256>>>(h, als, ald, b0, ln1g, ln1b, feat, n);

    k_gemm_attn8_tc<<<nb_gemm, 256>>>(feat, W1, as1, ad1, h, als, ald, n);
    k_agg8<<<nb_warp, 256>>>(h, als, ald, b1, ln2g, ln2b, feat, n);

    k_gemm_attn1_tc<<<nb_gemm, 256>>>(feat, W2, as2, ad2, h, als, ald, n);
    k_agg1_lsm<<<nb_warp, 256>>>(h, als, ald, b2, out, n);
}

// round 7
// speedup vs baseline: 1.2627x; 1.2627x over previous
#include <cuda_runtime.h>
#include <cuda_fp16.h>
#include <math.h>
#include <stdint.h>

#define NN 100000
#define NE 1600000
#define ET (NE + NN)
#define LRELU 0.2f

// ---------- scratch ----------
__device__ __half g_h[(size_t)NN * 128];    // fp16 post-GEMM features
__device__ float g_feat[(size_t)NN * 128];
__device__ float g_als[(size_t)NN * 8];
__device__ float g_ald[(size_t)NN * 8];
__device__ __half g_ew[(size_t)ET * 8];     // per-edge softmax weights (8 heads)
__device__ int   g_rowptr[NN + 1];
__device__ int   g_cnt[NN];
__device__ int   g_srcs[ET];
__device__ int   g_dsts[ET];
__device__ int   g_part[128];

// ---------------------- CSR build ----------------------
__global__ void k_init_cnt(int n) {
    int i = blockIdx.x * blockDim.x + threadIdx.x;
    if (i < n) g_cnt[i] = 1;
}
__global__ void k_count(const int* __restrict__ dst, int e) {
    int i = blockIdx.x * blockDim.x + threadIdx.x;
    if (i < e) atomicAdd(&g_cnt[dst[i]], 1);
}
__global__ void k_scan1(int n) {
    __shared__ int sh[1024];
    int tid = threadIdx.x;
    int i = blockIdx.x * 1024 + tid;
    int v = (i < n) ? g_cnt[i] : 0;
    sh[tid] = v;
    __syncthreads();
    #pragma unroll
    for (int o = 1; o < 1024; o <<= 1) {
        int t = (tid >= o) ? sh[tid - o] : 0;
        __syncthreads();
        sh[tid] += t;
        __syncthreads();
    }
    if (i < n) g_rowptr[i] = sh[tid] - v;
    if (tid == 1023) g_part[blockIdx.x] = sh[1023];
}
__global__ void k_scan2(int nb) {
    __shared__ int sh[128];
    int tid = threadIdx.x;
    int v = (tid < nb) ? g_part[tid] : 0;
    sh[tid] = v;
    __syncthreads();
    #pragma unroll
    for (int o = 1; o < 128; o <<= 1) {
        int t = (tid >= o) ? sh[tid - o] : 0;
        __syncthreads();
        sh[tid] += t;
        __syncthreads();
    }
    if (tid < nb) g_part[tid] = sh[tid] - v;
}
// scan finalize + self-loop placement + cursor init (fused)
__global__ void k_scan3(int n, int etot) {
    int i = blockIdx.x * 1024 + threadIdx.x;
    if (i < n) {
        int p = g_rowptr[i] + g_part[blockIdx.x];
        g_rowptr[i] = p;
        g_srcs[p] = i;
        g_dsts[p] = i;
        g_cnt[i] = p + 1;
    }
    if (i == 0) g_rowptr[n] = etot;
}
__global__ void k_scatter(const int* __restrict__ src, const int* __restrict__ dst, int e) {
    int i = blockIdx.x * blockDim.x + threadIdx.x;
    if (i < e) {
        int d = dst[i];
        int pos = atomicAdd(&g_cnt[d], 1);
        g_srcs[pos] = src[i];
        g_dsts[pos] = d;
    }
}

// ---------------------- edge weight precompute ----------------------
// 8 heads: w[i][h] = exp(leaky_relu(als[src][h] + ald[dst][h]))
__global__ __launch_bounds__(256) void k_edgew8(const float* __restrict__ als,
                                                const float* __restrict__ ald,
                                                int etot) {
    int i = blockIdx.x * blockDim.x + threadIdx.x;
    if (i >= etot) return;
    int s = g_srcs[i], d = g_dsts[i];
    float4 a0 = *(const float4*)(als + (size_t)s * 8);
    float4 a1 = *(const float4*)(als + (size_t)s * 8 + 4);
    float4 b0 = *(const float4*)(ald + (size_t)d * 8);
    float4 b1 = *(const float4*)(ald + (size_t)d * 8 + 4);
    float x[8] = {a0.x + b0.x, a0.y + b0.y, a0.z + b0.z, a0.w + b0.w,
                  a1.x + b1.x, a1.y + b1.y, a1.z + b1.z, a1.w + b1.w};
    __half hw[8];
    #pragma unroll
    for (int h = 0; h < 8; h++) {
        float v = (x[h] > 0.f) ? x[h] : LRELU * x[h];
        hw[h] = __float2half_rn(__expf(v));
    }
    *(uint4*)(g_ew + (size_t)i * 8) = *(uint4*)hw;
}

// 1 head
__global__ __launch_bounds__(256) void k_edgew1(const float* __restrict__ als,
                                                const float* __restrict__ ald,
                                                int etot) {
    int i = blockIdx.x * blockDim.x + threadIdx.x;
    if (i >= etot) return;
    float x = als[g_srcs[i]] + ald[g_dsts[i]];
    x = (x > 0.f) ? x : LRELU * x;
    g_ew[i] = __float2half_rn(__expf(x));
}

// ---------------------- tf32 helpers ----------------------
__device__ __forceinline__ uint32_t f2tf32(float x) {
    uint32_t r;
    asm("cvt.rna.tf32.f32 %0, %1;" : "=r"(r) : "f"(x));
    return r;
}
#define MMA_TF32(d, a, b) \
    asm volatile("mma.sync.aligned.m16n8k8.row.col.f32.tf32.tf32.f32 " \
        "{%0,%1,%2,%3}, {%4,%5,%6,%7}, {%8,%9}, {%0,%1,%2,%3};" \
        : "+f"((d)[0]), "+f"((d)[1]), "+f"((d)[2]), "+f"((d)[3]) \
        : "r"((a)[0]), "r"((a)[1]), "r"((a)[2]), "r"((a)[3]), \
          "r"((b)[0]), "r"((b)[1]))

// ---------------------- TC GEMM 128x128 + attn coefs (8 heads x 16) ----------------------
__global__ __launch_bounds__(256) void k_gemm_attn8_tc(
    const float* __restrict__ A, const float* __restrict__ W,
    const float* __restrict__ asr, const float* __restrict__ adr,
    __half* __restrict__ H, float* __restrict__ als, float* __restrict__ ald, int n)
{
    __shared__ __align__(16) uint32_t As[128 * 36];
    __shared__ __align__(16) uint32_t Bs[32 * 136];
    int tid = threadIdx.x;
    int wid = tid >> 5, lane = tid & 31;
    int warp_m = wid >> 1, warp_n = wid & 1;
    int g = lane >> 2, c = lane & 3;
    int row0 = blockIdx.x * 128;

    float acc[2][8][4];
    #pragma unroll
    for (int mt = 0; mt < 2; mt++)
        #pragma unroll
        for (int nt = 0; nt < 8; nt++)
            #pragma unroll
            for (int j = 0; j < 4; j++) acc[mt][nt][j] = 0.f;

    for (int k0 = 0; k0 < 128; k0 += 32) {
        #pragma unroll
        for (int l = 0; l < 4; l++) {
            int idx = tid + l * 256;
            int r = idx >> 3, kq = idx & 7;
            int gr = row0 + r;
            float4 v = make_float4(0.f, 0.f, 0.f, 0.f);
            if (gr < n) v = *(const float4*)(A + (size_t)gr * 128 + k0 + kq * 4);
            uint4 u = {f2tf32(v.x), f2tf32(v.y), f2tf32(v.z), f2tf32(v.w)};
            *(uint4*)&As[r * 36 + kq * 4] = u;
        }
        #pragma unroll
        for (int l = 0; l < 4; l++) {
            int idx = tid + l * 256;
            int kr = idx >> 5, cq = idx & 31;
            float4 v = *(const float4*)(W + (size_t)(k0 + kr) * 128 + cq * 4);
            uint4 u = {f2tf32(v.x), f2tf32(v.y), f2tf32(v.z), f2tf32(v.w)};
            *(uint4*)&Bs[kr * 136 + cq * 4] = u;
        }
        __syncthreads();
        #pragma unroll
        for (int ks = 0; ks < 4; ks++) {
            uint32_t bf[8][2];
            #pragma unroll
            for (int nt = 0; nt < 8; nt++) {
                int col = warp_n * 64 + nt * 8 + g;
                bf[nt][0] = Bs[(ks * 8 + c) * 136 + col];
                bf[nt][1] = Bs[(ks * 8 + c + 4) * 136 + col];
            }
            #pragma unroll
            for (int mt = 0; mt < 2; mt++) {
                int row = warp_m * 32 + mt * 16 + g;
                uint32_t af[4];
                af[0] = As[row * 36 + ks * 8 + c];
                af[1] = As[(row + 8) * 36 + ks * 8 + c];
                af[2] = As[row * 36 + ks * 8 + c + 4];
                af[3] = As[(row + 8) * 36 + ks * 8 + c + 4];
                #pragma unroll
                for (int nt = 0; nt < 8; nt++) MMA_TF32(acc[mt][nt], af, bf[nt]);
            }
        }
        __syncthreads();
    }

    #pragma unroll
    for (int mt = 0; mt < 2; mt++) {
        int r_lo = row0 + warp_m * 32 + mt * 16 + g;
        int r_hi = r_lo + 8;
        float sA0[4] = {0, 0, 0, 0}, sA1[4] = {0, 0, 0, 0};
        float sD0[4] = {0, 0, 0, 0}, sD1[4] = {0, 0, 0, 0};
        #pragma unroll
        for (int nt = 0; nt < 8; nt++) {
            int col = warp_n * 64 + nt * 8 + c * 2;
            int hh = nt >> 1;
            float as0 = asr[col], as1 = asr[col + 1];
            float ad0 = adr[col], ad1 = adr[col + 1];
            float* d = acc[mt][nt];
            sA0[hh] = fmaf(d[0], as0, fmaf(d[1], as1, sA0[hh]));
            sA1[hh] = fmaf(d[2], as0, fmaf(d[3], as1, sA1[hh]));
            sD0[hh] = fmaf(d[0], ad0, fmaf(d[1], ad1, sD0[hh]));
            sD1[hh] = fmaf(d[2], ad0, fmaf(d[3], ad1, sD1[hh]));
            if (r_lo < n) *(__half2*)(H + (size_t)r_lo * 128 + col) = __floats2half2_rn(d[0], d[1]);
            if (r_hi < n) *(__half2*)(H + (size_t)r_hi * 128 + col) = __floats2half2_rn(d[2], d[3]);
        }
        #pragma unroll
        for (int hh = 0; hh < 4; hh++) {
            sA0[hh] += __shfl_xor_sync(0xFFFFFFFFu, sA0[hh], 1);
            sA0[hh] += __shfl_xor_sync(0xFFFFFFFFu, sA0[hh], 2);
            sA1[hh] += __shfl_xor_sync(0xFFFFFFFFu, sA1[hh], 1);
            sA1[hh] += __shfl_xor_sync(0xFFFFFFFFu, sA1[hh], 2);
            sD0[hh] += __shfl_xor_sync(0xFFFFFFFFu, sD0[hh], 1);
            sD0[hh] += __shfl_xor_sync(0xFFFFFFFFu, sD0[hh], 2);
            sD1[hh] += __shfl_xor_sync(0xFFFFFFFFu, sD1[hh], 1);
            sD1[hh] += __shfl_xor_sync(0xFFFFFFFFu, sD1[hh], 2);
        }
        if (c == 0) {
            #pragma unroll
            for (int hh = 0; hh < 4; hh++) {
                int hgl = warp_n * 4 + hh;
                if (r_lo < n) { als[(size_t)r_lo * 8 + hgl] = sA0[hh]; ald[(size_t)r_lo * 8 + hgl] = sD0[hh]; }
                if (r_hi < n) { als[(size_t)r_hi * 8 + hgl] = sA1[hh]; ald[(size_t)r_hi * 8 + hgl] = sD1[hh]; }
            }
        }
    }
}

// ---------------------- TC GEMM 128x64 + attn coefs (1 head x 64) ----------------------
__global__ __launch_bounds__(256) void k_gemm_attn1_tc(
    const float* __restrict__ A, const float* __restrict__ W,
    const float* __restrict__ asr, const float* __restrict__ adr,
    __half* __restrict__ H, float* __restrict__ als, float* __restrict__ ald, int n)
{
    __shared__ __align__(16) uint32_t As[128 * 36];
    __shared__ __align__(16) uint32_t Bs[32 * 72];
    int tid = threadIdx.x;
    int wid = tid >> 5, lane = tid & 31;
    int g = lane >> 2, c = lane & 3;
    int row0 = blockIdx.x * 128;

    float acc[8][4];
    #pragma unroll
    for (int nt = 0; nt < 8; nt++)
        #pragma unroll
        for (int j = 0; j < 4; j++) acc[nt][j] = 0.f;

    for (int k0 = 0; k0 < 128; k0 += 32) {
        #pragma unroll
        for (int l = 0; l < 4; l++) {
            int idx = tid + l * 256;
            int r = idx >> 3, kq = idx & 7;
            int gr = row0 + r;
            float4 v = make_float4(0.f, 0.f, 0.f, 0.f);
            if (gr < n) v = *(const float4*)(A + (size_t)gr * 128 + k0 + kq * 4);
            uint4 u = {f2tf32(v.x), f2tf32(v.y), f2tf32(v.z), f2tf32(v.w)};
            *(uint4*)&As[r * 36 + kq * 4] = u;
        }
        #pragma unroll
        for (int l = 0; l < 2; l++) {
            int idx = tid + l * 256;
            int kr = idx >> 4, cq = idx & 15;
            float4 v = *(const float4*)(W + (size_t)(k0 + kr) * 64 + cq * 4);
            uint4 u = {f2tf32(v.x), f2tf32(v.y), f2tf32(v.z), f2tf32(v.w)};
            *(uint4*)&Bs[kr * 72 + cq * 4] = u;
        }
        __syncthreads();
        #pragma unroll
        for (int ks = 0; ks < 4; ks++) {
            int row = wid * 16 + g;
            uint32_t af[4];
            af[0] = As[row * 36 + ks * 8 + c];
            af[1] = As[(row + 8) * 36 + ks * 8 + c];
            af[2] = As[row * 36 + ks * 8 + c + 4];
            af[3] = As[(row + 8) * 36 + ks * 8 + c + 4];
            #pragma unroll
            for (int nt = 0; nt < 8; nt++) {
                int col = nt * 8 + g;
                uint32_t bf[2];
                bf[0] = Bs[(ks * 8 + c) * 72 + col];
                bf[1] = Bs[(ks * 8 + c + 4) * 72 + col];
                MMA_TF32(acc[nt], af, bf);
            }
        }
        __syncthreads();
    }

    int r_lo = row0 + wid * 16 + g;
    int r_hi = r_lo + 8;
    float sA0 = 0.f, sA1 = 0.f, sD0 = 0.f, sD1 = 0.f;
    #pragma unroll
    for (int nt = 0; nt < 8; nt++) {
        int col = nt * 8 + c * 2;
        float as0 = asr[col], as1 = asr[col + 1];
        float ad0 = adr[col], ad1 = adr[col + 1];
        float* d = acc[nt];
        sA0 = fmaf(d[0], as0, fmaf(d[1], as1, sA0));
        sA1 = fmaf(d[2], as0, fmaf(d[3], as1, sA1));
        sD0 = fmaf(d[0], ad0, fmaf(d[1], ad1, sD0));
        sD1 = fmaf(d[2], ad0, fmaf(d[3], ad1, sD1));
        if (r_lo < n) *(__half2*)(H + (size_t)r_lo * 64 + col) = __floats2half2_rn(d[0], d[1]);
        if (r_hi < n) *(__half2*)(H + (size_t)r_hi * 64 + col) = __floats2half2_rn(d[2], d[3]);
    }
    sA0 += __shfl_xor_sync(0xFFFFFFFFu, sA0, 1); sA0 += __shfl_xor_sync(0xFFFFFFFFu, sA0, 2);
    sA1 += __shfl_xor_sync(0xFFFFFFFFu, sA1, 1); sA1 += __shfl_xor_sync(0xFFFFFFFFu, sA1, 2);
    sD0 += __shfl_xor_sync(0xFFFFFFFFu, sD0, 1); sD0 += __shfl_xor_sync(0xFFFFFFFFu, sD0, 2);
    sD1 += __shfl_xor_sync(0xFFFFFFFFu, sD1, 1); sD1 += __shfl_xor_sync(0xFFFFFFFFu, sD1, 2);
    if (c == 0) {
        if (r_lo < n) { als[r_lo] = sA0; ald[r_lo] = sD0; }
        if (r_hi < n) { als[r_hi] = sA1; ald[r_hi] = sD1; }
    }
}

// ---------------------- aggregation (8 heads x 16) + fused LN+ReLU ----------------------
// consumes precomputed edge weights: no exp/shfl/divergence in the loop
__global__ __launch_bounds__(256) void k_agg8(
    const __half* __restrict__ H, const float* __restrict__ bias,
    const float* __restrict__ lng, const float* __restrict__ lnb,
    float* __restrict__ out, int n)
{
    int w = (blockIdx.x * blockDim.x + threadIdx.x) >> 5;
    if (w >= n) return;
    int lane = threadIdx.x & 31;
    int s = g_rowptr[w], e2 = g_rowptr[w + 1];
    int hd = lane >> 2;
    int d0 = lane * 4;
    float denom = 0.f;
    float ax = 0.f, ay = 0.f, az = 0.f, aw = 0.f;

    int i = s;
    for (; i + 4 <= e2; i += 4) {
        int sv[4];
        float wv[4];
        #pragma unroll
        for (int j = 0; j < 4; j++) sv[j] = g_srcs[i + j];
        #pragma unroll
        for (int j = 0; j < 4; j++) wv[j] = __half2float(g_ew[(size_t)(i + j) * 8 + hd]);
        uint2 raw[4];
        #pragma unroll
        for (int j = 0; j < 4; j++) raw[j] = *(const uint2*)(H + (size_t)sv[j] * 128 + d0);
        #pragma unroll
        for (int j = 0; j < 4; j++) {
            denom += wv[j];
            float2 f01 = __half22float2(*(__half2*)&raw[j].x);
            float2 f23 = __half22float2(*(__half2*)&raw[j].y);
            ax = fmaf(wv[j], f01.x, ax); ay = fmaf(wv[j], f01.y, ay);
            az = fmaf(wv[j], f23.x, az); aw = fmaf(wv[j], f23.y, aw);
        }
    }
    for (; i < e2; ++i) {
        int s0 = g_srcs[i];
        float w0 = __half2float(g_ew[(size_t)i * 8 + hd]);
        denom += w0;
        uint2 raw = *(const uint2*)(H + (size_t)s0 * 128 + d0);
        float2 f01 = __half22float2(*(__half2*)&raw.x);
        float2 f23 = __half22float2(*(__half2*)&raw.y);
        ax = fmaf(w0, f01.x, ax); ay = fmaf(w0, f01.y, ay);
        az = fmaf(w0, f23.x, az); aw = fmaf(w0, f23.y, aw);
    }

    float inv = 1.f / denom;
    float4 bv = *(const float4*)(bias + d0);
    float ox = fmaf(ax, inv, bv.x);
    float oy = fmaf(ay, inv, bv.y);
    float oz = fmaf(az, inv, bv.z);
    float ow = fmaf(aw, inv, bv.w);

    float sm = ox + oy + oz + ow;
    #pragma unroll
    for (int o = 16; o; o >>= 1) sm += __shfl_xor_sync(0xFFFFFFFFu, sm, o);
    float mu = sm * (1.f / 128.f);
    float dx = ox - mu, dy = oy - mu, dz = oz - mu, dw = ow - mu;
    float q = dx * dx + dy * dy + dz * dz + dw * dw;
    #pragma unroll
    for (int o = 16; o; o >>= 1) q += __shfl_xor_sync(0xFFFFFFFFu, q, o);
    float rstd = rsqrtf(q * (1.f / 128.f) + 1e-5f);
    float4 gg = *(const float4*)(lng + d0);
    float4 bb = *(const float4*)(lnb + d0);
    ox = fmaxf(fmaf(dx * rstd, gg.x, bb.x), 0.f);
    oy = fmaxf(fmaf(dy * rstd, gg.y, bb.y), 0.f);
    oz = fmaxf(fmaf(dz * rstd, gg.z, bb.z), 0.f);
    ow = fmaxf(fmaf(dw * rstd, gg.w, bb.w), 0.f);
    float4 o4 = {ox, oy, oz, ow};
    *(float4*)(out + (size_t)w * 128 + d0) = o4;
}

// ---------------------- aggregation (1 head x 64) + log_softmax ----------------------
__global__ __launch_bounds__(256) void k_agg1_lsm(
    const __half* __restrict__ H, const float* __restrict__ bias,
    float* __restrict__ out, int n)
{
    int w = (blockIdx.x * blockDim.x + threadIdx.x) >> 5;
    if (w >= n) return;
    int lane = threadIdx.x & 31;
    int s = g_rowptr[w], e2 = g_rowptr[w + 1];
    int d0 = lane * 2;

    float denom = 0.f, acc0 = 0.f, acc1 = 0.f;
    int i = s;
    for (; i + 4 <= e2; i += 4) {
        int sv[4];
        float wv[4];
        #pragma unroll
        for (int j = 0; j < 4; j++) sv[j] = g_srcs[i + j];
        #pragma unroll
        for (int j = 0; j < 4; j++) wv[j] = __half2float(g_ew[i + j]);
        __half2 hv[4];
        #pragma unroll
        for (int j = 0; j < 4; j++) hv[j] = *(const __half2*)(H + (size_t)sv[j] * 64 + d0);
        #pragma unroll
        for (int j = 0; j < 4; j++) {
            denom += wv[j];
            float2 f = __half22float2(hv[j]);
            acc0 = fmaf(wv[j], f.x, acc0);
            acc1 = fmaf(wv[j], f.y, acc1);
        }
    }
    for (; i < e2; ++i) {
        int s0 = g_srcs[i];
        float w0 = __half2float(g_ew[i]);
        denom += w0;
        float2 f = __half22float2(*(const __half2*)(H + (size_t)s0 * 64 + d0));
        acc0 = fmaf(w0, f.x, acc0); acc1 = fmaf(w0, f.y, acc1);
    }
    float inv = 1.f / denom;
    float v0 = fmaf(acc0, inv, bias[d0]);
    float v1 = fmaf(acc1, inv, bias[d0 + 1]);
    float mx = fmaxf(v0, v1);
    #pragma unroll
    for (int o = 16; o; o >>= 1) mx = fmaxf(mx, __shfl_xor_sync(0xFFFFFFFFu, mx, o));
    float se = __expf(v0 - mx) + __expf(v1 - mx);
    #pragma unroll
    for (int o = 16; o; o >>= 1) se += __shfl_xor_sync(0xFFFFFFFFu, se, o);
    float lse = mx + __logf(se);
    out[(size_t)w * 64 + d0] = v0 - lse;
    out[(size_t)w * 64 + d0 + 1] = v1 - lse;
}

// ---------------------- launcher ----------------------
extern "C" void kernel_launch(void* const* d_in, const int* in_sizes, int n_in,
                              void* d_out, int out_size) {
    const float* x   = (const float*)d_in[0];
    const int*   ei  = (const int*)d_in[1];
    const float* W0  = (const float*)d_in[2];
    const float* as0 = (const float*)d_in[3];
    const float* ad0 = (const float*)d_in[4];
    const float* b0  = (const float*)d_in[5];
    const float* W1  = (const float*)d_in[6];
    const float* as1 = (const float*)d_in[7];
    const float* ad1 = (const float*)d_in[8];
    const float* b1  = (const float*)d_in[9];
    const float* W2  = (const float*)d_in[10];
    const float* as2 = (const float*)d_in[11];
    const float* ad2 = (const float*)d_in[12];
    const float* b2  = (const float*)d_in[13];
    const float* ln1g = (const float*)d_in[14];
    const float* ln1b = (const float*)d_in[15];
    const float* ln2g = (const float*)d_in[16];
    const float* ln2b = (const float*)d_in[17];
    float* out = (float*)d_out;

    const int n = in_sizes[0] / 128;
    const int e = in_sizes[1] / 2;
    const int etot = e + n;
    const int* src = ei;
    const int* dst = ei + e;

    __half* h;
    float *feat, *als, *ald;
    cudaGetSymbolAddress((void**)&h, g_h);
    cudaGetSymbolAddress((void**)&feat, g_feat);
    cudaGetSymbolAddress((void**)&als, g_als);
    cudaGetSymbolAddress((void**)&ald, g_ald);

    const int nb_nodes256 = (n + 255) / 256;
    const int nb_edges256 = (e + 255) / 256;
    const int nb_etot256 = (etot + 255) / 256;
    const int nb_scan = (n + 1023) / 1024;
    const int nb_warp = (n * 32 + 255) / 256;
    const int nb_gemm = (n + 127) / 128;

    k_init_cnt<<<nb_nodes256, 256>>>(n);
    k_count<<<nb_edges256, 256>>>(dst, e);
    k_scan1<<<nb_scan, 1024>>>(n);
    k_scan2<<<1, 128>>>(nb_scan);
    k_scan3<<<nb_scan, 1024>>>(n, etot);
    k_scatter<<<nb_edges256, 256>>>(src, dst, e);

    k_gemm_attn8_tc<<<nb_gemm, 256>>>(x, W0, as0, ad0, h, als, ald, n);
    k_edgew8<<<nb_etot256, 256>>>(als, ald, etot);
    k_agg8<<<nb_warp, 256>>>(h, b0, ln1g, ln1b, feat, n);

    k_gemm_attn8_tc<<<nb_gemm, 256>>>(feat, W1, as1, ad1, h, als, ald, n);
    k_edgew8<<<nb_etot256, 256>>>(als, ald, etot);
    k_agg8<<<nb_warp, 256>>>(h, b1, ln2g, ln2b, feat, n);

    k_gemm_attn1_tc<<<nb_gemm, 256>>>(feat, W2, as2, ad2, h, als, ald, n);
    k_edgew1<<<nb_etot256, 256>>>(als, ald, etot);
    k_agg1_lsm<<<nb_warp, 256>>>(h, b2, out, n);
}